// round 3
// baseline (speedup 1.0000x reference)
#include <cuda_runtime.h>
#include <math.h>
#include <stdint.h>

#define BATCH 128
#define SEQ   256
#define HID   256
#define MROWS 32768
#define NBLK_SCAN 128

// ---------------- scratch (no allocations allowed) ----------------
__device__ float g_st1[(size_t)MROWS * 256];
__device__ float g_st2[(size_t)MROWS * 512];
__device__ float g_st3[(size_t)MROWS * 1024];
__device__ float g_u  [(size_t)MROWS * 1024];
__device__ float g_utr[(size_t)MROWS * 1024];   // [t][col 0..1023][b]
__device__ float g_hc[2][2][HID * BATCH];       // [buf][h=0/c=1][k*128+b]
__device__ unsigned g_bar_count;
__device__ unsigned g_bar_gen;

// ---------------- SGEMM: C[M,N] = A[M,K]@B[K,N] (+bias)(+accum)(+relu) ------
// M%128==0, N%128==0 required. 256 threads, 128x128 tile, BK=8, 8x8/thread.
__global__ __launch_bounds__(256, 2) void sgemm_kernel(
    const float* __restrict__ A, const float* __restrict__ B,
    const float* __restrict__ bias, float* __restrict__ C,
    int M, int N, int K, int relu, int accum)
{
    __shared__ float As[8][128];
    __shared__ float Bs[8][128];
    const int tid = threadIdx.x;
    const int tx = tid & 15, ty = tid >> 4;
    const float* Ab = A + (size_t)blockIdx.y * 128 * K;
    const float* Bb = B + blockIdx.x * 128;

    float acc[8][8];
#pragma unroll
    for (int i = 0; i < 8; i++)
#pragma unroll
        for (int j = 0; j < 8; j++) acc[i][j] = 0.f;

    const int aRow = tid >> 1, aCol = (tid & 1) << 2;
    const int bRow = tid >> 5, bCol = (tid & 31) << 2;
    const bool kvec = ((K & 7) == 0);

    for (int k0 = 0; k0 < K; k0 += 8) {
        if (kvec) {
            float4 av = *(const float4*)(Ab + (size_t)aRow * K + k0 + aCol);
            As[aCol + 0][aRow] = av.x;
            As[aCol + 1][aRow] = av.y;
            As[aCol + 2][aRow] = av.z;
            As[aCol + 3][aRow] = av.w;
        } else {
#pragma unroll
            for (int i2 = 0; i2 < 4; i2++) {
                int kk = aCol + i2;
                As[kk][aRow] = (k0 + kk < K) ? Ab[(size_t)aRow * K + k0 + kk] : 0.f;
            }
        }
        if (k0 + bRow < K) {
            float4 bv = *(const float4*)(Bb + (size_t)(k0 + bRow) * N + bCol);
            Bs[bRow][bCol + 0] = bv.x; Bs[bRow][bCol + 1] = bv.y;
            Bs[bRow][bCol + 2] = bv.z; Bs[bRow][bCol + 3] = bv.w;
        } else {
            Bs[bRow][bCol + 0] = 0.f; Bs[bRow][bCol + 1] = 0.f;
            Bs[bRow][bCol + 2] = 0.f; Bs[bRow][bCol + 3] = 0.f;
        }
        __syncthreads();
#pragma unroll
        for (int kk = 0; kk < 8; kk++) {
            float av[8], bv[8];
#pragma unroll
            for (int i = 0; i < 8; i++) av[i] = As[kk][ty * 8 + i];
#pragma unroll
            for (int j = 0; j < 8; j++) bv[j] = Bs[kk][tx * 8 + j];
#pragma unroll
            for (int i = 0; i < 8; i++)
#pragma unroll
                for (int j = 0; j < 8; j++)
                    acc[i][j] += av[i] * bv[j];
        }
        __syncthreads();
    }

    const int row0 = blockIdx.y * 128 + ty * 8;
    const int col0 = blockIdx.x * 128 + tx * 8;
#pragma unroll
    for (int i = 0; i < 8; i++) {
        float* Cp = C + (size_t)(row0 + i) * N + col0;
#pragma unroll
        for (int j = 0; j < 8; j++) {
            float v = acc[i][j];
            if (bias)  v += bias[col0 + j];
            if (accum) v += Cp[j];
            if (relu)  v = fmaxf(v, 0.f);
            Cp[j] = v;
        }
    }
}

// ---------------- transpose u[(b*SEQ+t)*1024+n] -> g_utr[(t*1024+n)*128+b] --
__global__ void transpose_u_kernel(const float* __restrict__ u)
{
    __shared__ float tile[32][33];
    const int nt = blockIdx.x;   // 0..31
    const int t  = blockIdx.y;   // 0..255
    const int bt = blockIdx.z;   // 0..3
    const int tx = threadIdx.x, ty = threadIdx.y;  // 32x8
#pragma unroll
    for (int i = 0; i < 4; i++) {
        int b = bt * 32 + ty + i * 8;
        int n = nt * 32 + tx;
        tile[ty + i * 8][tx] = u[((size_t)(b * SEQ + t)) * 1024 + n];
    }
    __syncthreads();
#pragma unroll
    for (int i = 0; i < 4; i++) {
        int n = nt * 32 + ty + i * 8;
        int b = bt * 32 + tx;
        g_utr[((size_t)t * 1024 + n) * 128 + b] = tile[tx][ty + i * 8];
    }
}

__global__ void barinit_kernel()
{
    g_bar_count = 0u;
    g_bar_gen = 0u;
}

// ---------------- persistent TLSTM scan -----------------------------------
__device__ __forceinline__ void grid_barrier(unsigned gen)
{
    __syncthreads();
    if (threadIdx.x == 0) {
        __threadfence();
        unsigned arrived = atomicAdd(&g_bar_count, 1u) + 1u;
        if (arrived == gen * NBLK_SCAN) {
            __threadfence();
            *(volatile unsigned*)&g_bar_gen = gen;
        } else {
            while (*(volatile unsigned*)&g_bar_gen < gen) { __nanosleep(64); }
        }
        __threadfence();
    }
    __syncthreads();
}

__device__ __forceinline__ float sigf(float x) { return 1.f / (1.f + __expf(-x)); }

__global__ __launch_bounds__(512, 1) void scan_kernel(
    const float* __restrict__ ts,
    const float* __restrict__ W_all, const float* __restrict__ W_all_b,
    const float* __restrict__ W_d,   const float* __restrict__ W_d_b,
    float* __restrict__ feat)
{
    extern __shared__ float sm[];
    float* Wsm = sm;                   // [2 jj][256 k][8 slots] (5 used) = 4096
    float* P   = sm + 4096;            // [8 ks][2 jj][128 b][5 g]        = 10240
    float* Bsm = sm + 4096 + 10240;    // [2 jj][5 g]

    const int tid = threadIdx.x;
    const int j0  = blockIdx.x * 2;

    // Stage weights once per launch
    {
        int jj = tid >> 8, k = tid & 255, j = j0 + jj;
        float* w = &Wsm[(jj * 256 + k) * 8];
        w[0] = W_all[k * 1024 + 0   + j];
        w[1] = W_all[k * 1024 + 256 + j];
        w[2] = W_all[k * 1024 + 512 + j];
        w[3] = W_all[k * 1024 + 768 + j];
        w[4] = W_d  [k * 256 + j];
    }
    if (tid < 10) {
        int jj = tid / 5, g = tid % 5, j = j0 + jj;
        Bsm[jj * 5 + g] = (g < 4) ? W_all_b[g * 256 + j] : W_d_b[j];
    }
    // zero h0/c0 (buffer 0) cooperatively
    {
        float* hc0 = &g_hc[0][0][0];
        for (int idx = blockIdx.x * 512 + tid; idx < 2 * HID * BATCH;
             idx += NBLK_SCAN * 512)
            hc0[idx] = 0.f;
    }
    grid_barrier(1);

    const int tx = tid & 31;
    const int jg = (tid >> 5) & 1;
    const int ks = tid >> 6;           // 0..7
    const int r0 = tx * 4;
    const float* wp = &Wsm[(jg * 256 + ks * 32) * 8];

    for (int t = 0; t < SEQ; t++) {
        const float* hT = &g_hc[t & 1][0][0];
        const float* cT = &g_hc[t & 1][1][0];
        float acc[4][5];
#pragma unroll
        for (int i = 0; i < 4; i++)
#pragma unroll
            for (int g = 0; g < 5; g++) acc[i][g] = 0.f;

        const int kbeg = ks * 32;
#pragma unroll 8
        for (int kk = 0; kk < 32; kk++) {
            int k = kbeg + kk;
            float4 h4 = *(const float4*)(hT + k * 128 + r0);
            float4 c4 = *(const float4*)(cT + k * 128 + r0);
            float4 w4 = *(const float4*)(wp + kk * 8);
            float  wd = wp[kk * 8 + 4];
            float hv[4] = {h4.x, h4.y, h4.z, h4.w};
            float cv[4] = {c4.x, c4.y, c4.z, c4.w};
#pragma unroll
            for (int i = 0; i < 4; i++) {
                acc[i][0] += hv[i] * w4.x;
                acc[i][1] += hv[i] * w4.y;
                acc[i][2] += hv[i] * w4.z;
                acc[i][3] += hv[i] * w4.w;
                acc[i][4] += cv[i] * wd;
            }
        }
        {
            float* Pp = &P[((ks * 2 + jg) * 128 + r0) * 5];
#pragma unroll
            for (int i = 0; i < 4; i++)
#pragma unroll
                for (int g = 0; g < 5; g++)
                    Pp[i * 5 + g] = acc[i][g];
        }
        __syncthreads();

        if (tid < 256) {
            int jj = tid >> 7, b = tid & 127, j = j0 + jj;
            float s[5];
#pragma unroll
            for (int g = 0; g < 5; g++) s[g] = Bsm[jj * 5 + g];
#pragma unroll
            for (int q = 0; q < 8; q++) {
                const float* Pq = &P[((q * 2 + jj) * 128 + b) * 5];
#pragma unroll
                for (int g = 0; g < 5; g++) s[g] += Pq[g];
            }
            const float* up = g_utr + ((size_t)t * 1024 + j) * 128 + b;
            float f  = sigf(s[0] + up[0 * 256 * 128]);
            float ii = sigf(s[1] + up[1 * 256 * 128]);
            float o  = sigf(s[2] + up[2 * 256 * 128]);
            float ct = sigf(s[3] + up[3 * 256 * 128]);
            float d  = tanhf(s[4]);
            float tt = ts[b * SEQ + t];
            float cprev = cT[j * 128 + b];
            float c_adj = (cprev - d) + d * tt;
            float cn = f * c_adj + ii * ct;
            float hn = o * tanhf(cn);
            g_hc[(t + 1) & 1][0][j * 128 + b] = hn;
            g_hc[(t + 1) & 1][1][j * 128 + b] = cn;
            feat[((size_t)b * SEQ + t) * HID + j] = hn;
        }
        grid_barrier((unsigned)(t + 2));
    }
}

// ---------------- classifier: out[m] = feat[m,:] . cls_w + cls_b -----------
__global__ void cls_kernel(const float* __restrict__ feat,
                           const float* __restrict__ w,
                           const float* __restrict__ bias,
                           float* __restrict__ out)
{
    int lane = threadIdx.x & 31;
    int wid  = (blockIdx.x * blockDim.x + threadIdx.x) >> 5;
    if (wid >= MROWS) return;
    const float* fr = feat + (size_t)wid * HID;
    float s = 0.f;
#pragma unroll
    for (int i = 0; i < 8; i++) s += fr[lane + 32 * i] * w[lane + 32 * i];
#pragma unroll
    for (int off = 16; off > 0; off >>= 1)
        s += __shfl_down_sync(0xffffffffu, s, off);
    if (lane == 0) out[wid] = s + bias[0];
}

// ---------------------------------------------------------------------------
extern "C" void kernel_launch(void* const* d_in, const int* in_sizes, int n_in,
                              void* d_out, int out_size)
{
    const float* x       = (const float*)d_in[0];
    const float* stages  = (const float*)d_in[1];
    const float* tsmp    = (const float*)d_in[2];
    const float* se_w1   = (const float*)d_in[3];
    const float* se_b1   = (const float*)d_in[4];
    const float* se_w2   = (const float*)d_in[5];
    const float* se_b2   = (const float*)d_in[6];
    const float* se_w3   = (const float*)d_in[7];
    const float* se_b3   = (const float*)d_in[8];
    const float* W_all_w = (const float*)d_in[9];
    const float* W_all_b = (const float*)d_in[10];
    const float* U_all_w = (const float*)d_in[11];
    const float* U_all_b = (const float*)d_in[12];
    const float* W_d_w   = (const float*)d_in[13];
    const float* W_d_b   = (const float*)d_in[14];
    const float* cls_w   = (const float*)d_in[15];
    const float* cls_b   = (const float*)d_in[16];

    float* out  = (float*)d_out;          // [32768, 1]
    float* feat = out + MROWS;            // [32768, 256]

    void *p_st1, *p_st2, *p_st3, *p_u;
    cudaGetSymbolAddress(&p_st1, g_st1);
    cudaGetSymbolAddress(&p_st2, g_st2);
    cudaGetSymbolAddress(&p_st3, g_st3);
    cudaGetSymbolAddress(&p_u,   g_u);
    float* st1 = (float*)p_st1;
    float* st2 = (float*)p_st2;
    float* st3 = (float*)p_st3;
    float* u   = (float*)p_u;

    // barrier state reset
    barinit_kernel<<<1, 1>>>();

    // stage-embedding MLP
    sgemm_kernel<<<dim3(2, 256), 256>>>(stages, se_w1, se_b1, st1,
                                        MROWS, 256, 67, 1, 0);
    sgemm_kernel<<<dim3(4, 256), 256>>>(st1, se_w2, se_b2, st2,
                                        MROWS, 512, 256, 1, 0);
    sgemm_kernel<<<dim3(8, 256), 256>>>(st2, se_w3, se_b3, st3,
                                        MROWS, 1024, 512, 1, 0);

    // u = [x | st3] @ U_all_w + U_all_b  (two GEMMs, second accumulates)
    sgemm_kernel<<<dim3(8, 256), 256>>>(x, U_all_w, U_all_b, u,
                                        MROWS, 1024, 1024, 0, 0);
    sgemm_kernel<<<dim3(8, 256), 256>>>(st3, U_all_w + (size_t)1024 * 1024,
                                        nullptr, u, MROWS, 1024, 1024, 0, 1);

    // transpose u to [t][col][b]
    transpose_u_kernel<<<dim3(32, 256, 4), dim3(32, 8)>>>(u);

    // persistent scan
    const int scan_smem = (4096 + 10240 + 16) * (int)sizeof(float);
    cudaFuncSetAttribute(scan_kernel,
                         cudaFuncAttributeMaxDynamicSharedMemorySize, scan_smem);
    scan_kernel<<<NBLK_SCAN, 512, scan_smem>>>(tsmp, W_all_w, W_all_b,
                                               W_d_w, W_d_b, feat);

    // classifier
    cls_kernel<<<4096, 256>>>(feat, cls_w, cls_b, out);
}

// round 5
// speedup vs baseline: 2.1158x; 2.1158x over previous
#include <cuda_runtime.h>
#include <math.h>
#include <stdint.h>

#define BATCH 128
#define SEQ   256
#define HID   256
#define MROWS 32768
#define NBLK_SCAN 128

// ---------------- scratch (no allocations allowed) ----------------
__device__ float g_st1[(size_t)MROWS * 256];
__device__ float g_st2[(size_t)MROWS * 512];
__device__ float g_st3[(size_t)MROWS * 1024];
__device__ float g_u  [(size_t)MROWS * 1024];
__device__ float g_utr[(size_t)MROWS * 1024];   // [t][col 0..1023][b]
__device__ float g_hc[2][2][HID * BATCH];       // [buf][h=0/c=1][k*128+b]
__device__ float g_w2t[512 * 256];              // se_w2^T  [512,256]
__device__ float g_w3t[1024 * 512];             // se_w3^T  [1024,512]
__device__ float g_uT [1024 * 2048];            // U_all_w^T [1024,2048]
__device__ unsigned g_bar_count;
__device__ unsigned g_bar_gen;

// ============================ PTX helpers (sm_80-class only!) ==============
__device__ __forceinline__ uint32_t smem_u32(const void* p) {
    uint32_t a;
    asm("{ .reg .u64 t; cvta.to.shared.u64 t, %1; cvt.u32.u64 %0, t; }"
        : "=r"(a) : "l"(p));
    return a;
}
#define CP_ASYNC16(dst, src) \
    asm volatile("cp.async.cg.shared.global [%0], [%1], 16;" \
                 :: "r"(dst), "l"(src) : "memory")
#define CP_ASYNC_COMMIT() asm volatile("cp.async.commit_group;" ::: "memory")
#define CP_ASYNC_WAIT(n)  asm volatile("cp.async.wait_group %0;" ::"n"(n):"memory")

#define LDMX4(r, a) \
    asm volatile("ldmatrix.sync.aligned.m8n8.x4.shared.b16 {%0,%1,%2,%3}, [%4];" \
        : "=r"((r)[0]), "=r"((r)[1]), "=r"((r)[2]), "=r"((r)[3]) : "r"(a))
#define LDMX2(r, a) \
    asm volatile("ldmatrix.sync.aligned.m8n8.x2.shared.b16 {%0,%1}, [%2];" \
        : "=r"((r)[0]), "=r"((r)[1]) : "r"(a))
#define MMA_TF32(d, a, b) \
    asm volatile("mma.sync.aligned.m16n8k8.row.col.f32.tf32.tf32.f32 " \
        "{%0,%1,%2,%3},{%4,%5,%6,%7},{%8,%9},{%0,%1,%2,%3};" \
        : "+f"((d)[0]), "+f"((d)[1]), "+f"((d)[2]), "+f"((d)[3]) \
        : "r"((a)[0]), "r"((a)[1]), "r"((a)[2]), "r"((a)[3]), \
          "r"((b)[0]), "r"((b)[1]))

__device__ __forceinline__ uint32_t swz128(uint32_t off) {
    return off ^ ((off >> 3) & 0x70);
}

// ================= tf32 mma.sync GEMM: C[M,N] = [A1|A2] @ BT^T =============
// A1: [M,K1] row-major for k<K1, A2: [M,K2] for k>=K1 (concat along K).
// BT: [N,Ktot] row-major (K-major / "col-major B" for mma).
// M%128==0, N%128==0, K1,K2 multiples of 32 (or K2=K1, A2=A1 if unsplit).
// CTA tile 128x128, BK=32, 8 warps (2M x 4N -> warp tile 64x32), 3-stage
// cp.async pipeline.
#define STAGES 3
#define STAGE_BYTES 32768                  // A 16KB + B 16KB
#define MMA_SMEM (STAGES * STAGE_BYTES)    // 98304

__global__ __launch_bounds__(256, 2)
void tc_gemm_kernel(const float* __restrict__ A1, int K1,
                    const float* __restrict__ A2, int K2,
                    const float* __restrict__ BT,
                    const float* __restrict__ bias,
                    float* __restrict__ C,
                    int M, int N, int Ktot, int relu)
{
    extern __shared__ char smc[];
    const uint32_t sbase = smem_u32(smc);
    const int tid  = threadIdx.x;
    const int wid  = tid >> 5, lane = tid & 31;
    const int n0   = blockIdx.x * 128;
    const int m0   = blockIdx.y * 128;
    const int NCH  = Ktot >> 5;
    const int wm   = wid & 1;     // 0..1  -> M offset wm*64
    const int wn   = wid >> 1;    // 0..3  -> N offset wn*32

    float acc[4][4][4];
#pragma unroll
    for (int mt = 0; mt < 4; mt++)
#pragma unroll
        for (int nt = 0; nt < 4; nt++)
#pragma unroll
            for (int q = 0; q < 4; q++) acc[mt][nt][q] = 0.f;

    auto load_chunk = [&](int stage, int k0) {
        uint32_t sA = sbase + stage * STAGE_BYTES;
        uint32_t sB = sA + 16384;
        const float* Ak; int kl;
        if (k0 < K1) { Ak = A1 + k0; kl = K1; }
        else         { Ak = A2 + (k0 - K1); kl = K2; }
#pragma unroll
        for (int q = 0; q < 4; q++) {
            int u = tid + 256 * q;
            int r = u >> 3, c = (u & 7) << 4;
            CP_ASYNC16(sA + swz128((uint32_t)(r * 128 + c)),
                       (const char*)(Ak + (size_t)(m0 + r) * kl) + c);
        }
#pragma unroll
        for (int q = 0; q < 4; q++) {
            int u = tid + 256 * q;
            int r = u >> 3, c = (u & 7) << 4;
            CP_ASYNC16(sB + swz128((uint32_t)(r * 128 + c)),
                       (const char*)(BT + (size_t)(n0 + r) * Ktot + k0) + c);
        }
        CP_ASYNC_COMMIT();
    };

    load_chunk(0, 0);
    load_chunk(1, 32);

    // precomputed fragment address components
    const int arow_l = (lane & 15);              // row within 16 (A frag)
    const int akb_l  = (lane >> 4) << 4;         // 0 or 16 bytes (A frag half)
    const int brow_l = (lane & 7);               // row within 8 (B frag)
    const int bkb_l  = ((lane >> 3) & 1) << 4;   // 0 or 16 bytes (B frag half)

    for (int i = 0; i < NCH; i++) {
        if (i < NCH - 1) { CP_ASYNC_WAIT(1); }
        else             { CP_ASYNC_WAIT(0); }
        __syncthreads();

        const int j = i + STAGES - 1;
        if (j < NCH) load_chunk(j % STAGES, j * 32);

        uint32_t sA = sbase + (i % STAGES) * STAGE_BYTES;
        uint32_t sB = sA + 16384;

#pragma unroll
        for (int s = 0; s < 4; s++) {
            uint32_t afr[4][4], bfr[4][2];
#pragma unroll
            for (int mt = 0; mt < 4; mt++) {
                int row = wm * 64 + mt * 16 + arow_l;
                uint32_t ad = sA + swz128((uint32_t)(row * 128 + s * 32 + akb_l));
                LDMX4(afr[mt], ad);
            }
#pragma unroll
            for (int nt = 0; nt < 4; nt++) {
                int row = wn * 32 + nt * 8 + brow_l;
                uint32_t bd = sB + swz128((uint32_t)(row * 128 + s * 32 + bkb_l));
                LDMX2(bfr[nt], bd);
            }
#pragma unroll
            for (int mt = 0; mt < 4; mt++)
#pragma unroll
                for (int nt = 0; nt < 4; nt++)
                    MMA_TF32(acc[mt][nt], afr[mt], bfr[nt]);
        }
        __syncthreads();
    }

    // epilogue: direct global stores, float2 per row-half
    const int mbase = m0 + wm * 64;
    const int nbase = n0 + wn * 32;
    const int cc = (lane & 3) * 2;
    const int rr = lane >> 2;
    float bx[4], by[4];
#pragma unroll
    for (int nt = 0; nt < 4; nt++) {
        bx[nt] = bias[nbase + nt * 8 + cc];
        by[nt] = bias[nbase + nt * 8 + cc + 1];
    }
#pragma unroll
    for (int mt = 0; mt < 4; mt++) {
        int r0 = mbase + mt * 16 + rr;
#pragma unroll
        for (int nt = 0; nt < 4; nt++) {
            int c0 = nbase + nt * 8 + cc;
            float v0 = acc[mt][nt][0] + bx[nt];
            float v1 = acc[mt][nt][1] + by[nt];
            float v2 = acc[mt][nt][2] + bx[nt];
            float v3 = acc[mt][nt][3] + by[nt];
            if (relu) {
                v0 = fmaxf(v0, 0.f); v1 = fmaxf(v1, 0.f);
                v2 = fmaxf(v2, 0.f); v3 = fmaxf(v3, 0.f);
            }
            float2 p0 = make_float2(v0, v1);
            float2 p1 = make_float2(v2, v3);
            *(float2*)(C + (size_t)r0 * N + c0) = p0;
            *(float2*)(C + (size_t)(r0 + 8) * N + c0) = p1;
        }
    }
}

// ---------------- weight transposes: [R,C] -> [C,R] ------------------------
__global__ void wtrans_kernel(const float* __restrict__ w2,
                              const float* __restrict__ w3,
                              const float* __restrict__ uw)
{
    const float* in; float* out; int R, C;
    if (blockIdx.z == 0)      { in = w2; out = g_w2t; R = 256;  C = 512;  }
    else if (blockIdx.z == 1) { in = w3; out = g_w3t; R = 512;  C = 1024; }
    else                      { in = uw; out = g_uT;  R = 2048; C = 1024; }
    if ((int)blockIdx.x * 32 >= C || (int)blockIdx.y * 32 >= R) return;
    __shared__ float t[32][33];
    const int tx = threadIdx.x, ty = threadIdx.y;
#pragma unroll
    for (int i = 0; i < 4; i++) {
        int r = blockIdx.y * 32 + ty + i * 8;
        int c = blockIdx.x * 32 + tx;
        t[ty + i * 8][tx] = in[(size_t)r * C + c];
    }
    __syncthreads();
#pragma unroll
    for (int i = 0; i < 4; i++) {
        int c = blockIdx.x * 32 + ty + i * 8;
        int r = blockIdx.y * 32 + tx;
        out[(size_t)c * R + r] = t[tx][ty + i * 8];
    }
}

// ---------------- SIMT SGEMM (se1 only, K=67) ------------------------------
__global__ __launch_bounds__(256, 2) void sgemm_kernel(
    const float* __restrict__ A, const float* __restrict__ B,
    const float* __restrict__ bias, float* __restrict__ C,
    int M, int N, int K, int relu, int accum)
{
    __shared__ float As[8][128];
    __shared__ float Bs[8][128];
    const int tid = threadIdx.x;
    const int tx = tid & 15, ty = tid >> 4;
    const float* Ab = A + (size_t)blockIdx.y * 128 * K;
    const float* Bb = B + blockIdx.x * 128;

    float acc[8][8];
#pragma unroll
    for (int i = 0; i < 8; i++)
#pragma unroll
        for (int j = 0; j < 8; j++) acc[i][j] = 0.f;

    const int aRow = tid >> 1, aCol = (tid & 1) << 2;
    const int bRow = tid >> 5, bCol = (tid & 31) << 2;
    const bool kvec = ((K & 7) == 0);

    for (int k0 = 0; k0 < K; k0 += 8) {
        if (kvec) {
            float4 av = *(const float4*)(Ab + (size_t)aRow * K + k0 + aCol);
            As[aCol + 0][aRow] = av.x; As[aCol + 1][aRow] = av.y;
            As[aCol + 2][aRow] = av.z; As[aCol + 3][aRow] = av.w;
        } else {
#pragma unroll
            for (int i2 = 0; i2 < 4; i2++) {
                int kk = aCol + i2;
                As[kk][aRow] = (k0 + kk < K) ? Ab[(size_t)aRow * K + k0 + kk] : 0.f;
            }
        }
        if (k0 + bRow < K) {
            float4 bv = *(const float4*)(Bb + (size_t)(k0 + bRow) * N + bCol);
            Bs[bRow][bCol + 0] = bv.x; Bs[bRow][bCol + 1] = bv.y;
            Bs[bRow][bCol + 2] = bv.z; Bs[bRow][bCol + 3] = bv.w;
        } else {
            Bs[bRow][bCol + 0] = 0.f; Bs[bRow][bCol + 1] = 0.f;
            Bs[bRow][bCol + 2] = 0.f; Bs[bRow][bCol + 3] = 0.f;
        }
        __syncthreads();
#pragma unroll
        for (int kk = 0; kk < 8; kk++) {
            float av[8], bv[8];
#pragma unroll
            for (int i = 0; i < 8; i++) av[i] = As[kk][ty * 8 + i];
#pragma unroll
            for (int j = 0; j < 8; j++) bv[j] = Bs[kk][tx * 8 + j];
#pragma unroll
            for (int i = 0; i < 8; i++)
#pragma unroll
                for (int j = 0; j < 8; j++)
                    acc[i][j] += av[i] * bv[j];
        }
        __syncthreads();
    }

    const int row0 = blockIdx.y * 128 + ty * 8;
    const int col0 = blockIdx.x * 128 + tx * 8;
#pragma unroll
    for (int i = 0; i < 8; i++) {
        float* Cp = C + (size_t)(row0 + i) * N + col0;
#pragma unroll
        for (int j = 0; j < 8; j++) {
            float v = acc[i][j];
            if (bias)  v += bias[col0 + j];
            if (accum) v += Cp[j];
            if (relu)  v = fmaxf(v, 0.f);
            Cp[j] = v;
        }
    }
}

// ---------------- transpose u[(b*SEQ+t)*1024+n] -> g_utr[(t*1024+n)*128+b] --
__global__ void transpose_u_kernel(const float* __restrict__ u)
{
    __shared__ float tile[32][33];
    const int nt = blockIdx.x;
    const int t  = blockIdx.y;
    const int bt = blockIdx.z;
    const int tx = threadIdx.x, ty = threadIdx.y;
#pragma unroll
    for (int i = 0; i < 4; i++) {
        int b = bt * 32 + ty + i * 8;
        int n = nt * 32 + tx;
        tile[ty + i * 8][tx] = u[((size_t)(b * SEQ + t)) * 1024 + n];
    }
    __syncthreads();
#pragma unroll
    for (int i = 0; i < 4; i++) {
        int n = nt * 32 + ty + i * 8;
        int b = bt * 32 + tx;
        g_utr[((size_t)t * 1024 + n) * 128 + b] = tile[tx][ty + i * 8];
    }
}

__global__ void barinit_kernel() { g_bar_count = 0u; g_bar_gen = 0u; }

// ---------------- persistent TLSTM scan -----------------------------------
__device__ __forceinline__ void grid_barrier(unsigned gen)
{
    __syncthreads();
    if (threadIdx.x == 0) {
        __threadfence();
        unsigned arrived = atomicAdd(&g_bar_count, 1u) + 1u;
        if (arrived == gen * NBLK_SCAN) {
            __threadfence();
            *(volatile unsigned*)&g_bar_gen = gen;
        } else {
            while (*(volatile unsigned*)&g_bar_gen < gen) { __nanosleep(64); }
        }
        __threadfence();
    }
    __syncthreads();
}

__device__ __forceinline__ float sigf(float x) { return 1.f / (1.f + __expf(-x)); }

__global__ __launch_bounds__(512, 1) void scan_kernel(
    const float* __restrict__ ts,
    const float* __restrict__ W_all, const float* __restrict__ W_all_b,
    const float* __restrict__ W_d,   const float* __restrict__ W_d_b,
    float* __restrict__ feat)
{
    extern __shared__ float smf[];
    float* Wsm = smf;
    float* P   = smf + 4096;
    float* Bsm = smf + 4096 + 10240;

    const int tid = threadIdx.x;
    const int j0  = blockIdx.x * 2;

    {
        int jj = tid >> 8, k = tid & 255, j = j0 + jj;
        float* w = &Wsm[(jj * 256 + k) * 8];
        w[0] = W_all[k * 1024 + 0   + j];
        w[1] = W_all[k * 1024 + 256 + j];
        w[2] = W_all[k * 1024 + 512 + j];
        w[3] = W_all[k * 1024 + 768 + j];
        w[4] = W_d  [k * 256 + j];
    }
    if (tid < 10) {
        int jj = tid / 5, g = tid % 5, j = j0 + jj;
        Bsm[jj * 5 + g] = (g < 4) ? W_all_b[g * 256 + j] : W_d_b[j];
    }
    {
        float* hc0 = &g_hc[0][0][0];
        for (int idx = blockIdx.x * 512 + tid; idx < 2 * HID * BATCH;
             idx += NBLK_SCAN * 512)
            hc0[idx] = 0.f;
    }
    grid_barrier(1);

    const int tx = tid & 31;
    const int jg = (tid >> 5) & 1;
    const int ks = tid >> 6;
    const int r0 = tx * 4;
    const float* wp = &Wsm[(jg * 256 + ks * 32) * 8];

    for (int t = 0; t < SEQ; t++) {
        const float* hT = &g_hc[t & 1][0][0];
        const float* cT = &g_hc[t & 1][1][0];
        float acc[4][5];
#pragma unroll
        for (int i = 0; i < 4; i++)
#pragma unroll
            for (int g = 0; g < 5; g++) acc[i][g] = 0.f;

        const int kbeg = ks * 32;
#pragma unroll 8
        for (int kk = 0; kk < 32; kk++) {
            int k = kbeg + kk;
            float4 h4 = *(const float4*)(hT + k * 128 + r0);
            float4 c4 = *(const float4*)(cT + k * 128 + r0);
            float4 w4 = *(const float4*)(wp + kk * 8);
            float  wd = wp[kk * 8 + 4];
            float hv[4] = {h4.x, h4.y, h4.z, h4.w};
            float cv[4] = {c4.x, c4.y, c4.z, c4.w};
#pragma unroll
            for (int i = 0; i < 4; i++) {
                acc[i][0] += hv[i] * w4.x;
                acc[i][1] += hv[i] * w4.y;
                acc[i][2] += hv[i] * w4.z;
                acc[i][3] += hv[i] * w4.w;
                acc[i][4] += cv[i] * wd;
            }
        }
        {
            float* Pp = &P[((ks * 2 + jg) * 128 + r0) * 5];
#pragma unroll
            for (int i = 0; i < 4; i++)
#pragma unroll
                for (int g = 0; g < 5; g++)
                    Pp[i * 5 + g] = acc[i][g];
        }
        __syncthreads();

        if (tid < 256) {
            int jj = tid >> 7, b = tid & 127, j = j0 + jj;
            float s[5];
#pragma unroll
            for (int g = 0; g < 5; g++) s[g] = Bsm[jj * 5 + g];
#pragma unroll
            for (int q = 0; q < 8; q++) {
                const float* Pq = &P[((q * 2 + jj) * 128 + b) * 5];
#pragma unroll
                for (int g = 0; g < 5; g++) s[g] += Pq[g];
            }
            const float* up = g_utr + ((size_t)t * 1024 + j) * 128 + b;
            float f  = sigf(s[0] + up[0 * 256 * 128]);
            float ii = sigf(s[1] + up[1 * 256 * 128]);
            float o  = sigf(s[2] + up[2 * 256 * 128]);
            float ct = sigf(s[3] + up[3 * 256 * 128]);
            float d  = tanhf(s[4]);
            float tt = ts[b * SEQ + t];
            float cprev = cT[j * 128 + b];
            float c_adj = (cprev - d) + d * tt;
            float cn = f * c_adj + ii * ct;
            float hn = o * tanhf(cn);
            g_hc[(t + 1) & 1][0][j * 128 + b] = hn;
            g_hc[(t + 1) & 1][1][j * 128 + b] = cn;
            feat[((size_t)b * SEQ + t) * HID + j] = hn;
        }
        grid_barrier((unsigned)(t + 2));
    }
}

// ---------------- classifier ----------------------------------------------
__global__ void cls_kernel(const float* __restrict__ feat,
                           const float* __restrict__ w,
                           const float* __restrict__ bias,
                           float* __restrict__ out)
{
    int lane = threadIdx.x & 31;
    int wid  = (blockIdx.x * blockDim.x + threadIdx.x) >> 5;
    if (wid >= MROWS) return;
    const float* fr = feat + (size_t)wid * HID;
    float s = 0.f;
#pragma unroll
    for (int i = 0; i < 8; i++) s += fr[lane + 32 * i] * w[lane + 32 * i];
#pragma unroll
    for (int off = 16; off > 0; off >>= 1)
        s += __shfl_down_sync(0xffffffffu, s, off);
    if (lane == 0) out[wid] = s + bias[0];
}

// ---------------------------------------------------------------------------
extern "C" void kernel_launch(void* const* d_in, const int* in_sizes, int n_in,
                              void* d_out, int out_size)
{
    const float* x       = (const float*)d_in[0];
    const float* stages  = (const float*)d_in[1];
    const float* tsmp    = (const float*)d_in[2];
    const float* se_w1   = (const float*)d_in[3];
    const float* se_b1   = (const float*)d_in[4];
    const float* se_w2   = (const float*)d_in[5];
    const float* se_b2   = (const float*)d_in[6];
    const float* se_w3   = (const float*)d_in[7];
    const float* se_b3   = (const float*)d_in[8];
    const float* W_all_w = (const float*)d_in[9];
    const float* W_all_b = (const float*)d_in[10];
    const float* U_all_w = (const float*)d_in[11];
    const float* U_all_b = (const float*)d_in[12];
    const float* W_d_w   = (const float*)d_in[13];
    const float* W_d_b   = (const float*)d_in[14];
    const float* cls_w   = (const float*)d_in[15];
    const float* cls_b   = (const float*)d_in[16];

    float* out  = (float*)d_out;
    float* feat = out + MROWS;

    void *p_st1, *p_st2, *p_st3, *p_u, *p_w2t, *p_w3t, *p_uT;
    cudaGetSymbolAddress(&p_st1, g_st1);
    cudaGetSymbolAddress(&p_st2, g_st2);
    cudaGetSymbolAddress(&p_st3, g_st3);
    cudaGetSymbolAddress(&p_u,   g_u);
    cudaGetSymbolAddress(&p_w2t, g_w2t);
    cudaGetSymbolAddress(&p_w3t, g_w3t);
    cudaGetSymbolAddress(&p_uT,  g_uT);
    float* st1 = (float*)p_st1;
    float* st2 = (float*)p_st2;
    float* st3 = (float*)p_st3;
    float* u   = (float*)p_u;
    float* w2t = (float*)p_w2t;
    float* w3t = (float*)p_w3t;
    float* uT  = (float*)p_uT;

    cudaFuncSetAttribute(tc_gemm_kernel,
                         cudaFuncAttributeMaxDynamicSharedMemorySize, MMA_SMEM);
    const int scan_smem = (4096 + 10240 + 16) * (int)sizeof(float);
    cudaFuncSetAttribute(scan_kernel,
                         cudaFuncAttributeMaxDynamicSharedMemorySize, scan_smem);

    // 1. transpose weights to K-major
    wtrans_kernel<<<dim3(32, 64, 3), dim3(32, 8)>>>(se_w2, se_w3, U_all_w);
    // 2. barrier reset
    barinit_kernel<<<1, 1>>>();
    // 3. se1 (K=67) stays SIMT
    sgemm_kernel<<<dim3(2, 256), 256>>>(stages, se_w1, se_b1, st1,
                                        MROWS, 256, 67, 1, 0);
    // 4. se2: [32768,256]@[256,512] tf32 mma
    tc_gemm_kernel<<<dim3(4, 256), 256, MMA_SMEM>>>(
        st1, 256, st1, 256, w2t, se_b2, st2, MROWS, 512, 256, 1);
    // 5. se3: [32768,512]@[512,1024]
    tc_gemm_kernel<<<dim3(8, 256), 256, MMA_SMEM>>>(
        st2, 512, st2, 512, w3t, se_b3, st3, MROWS, 1024, 512, 1);
    // 6. uproj fused: [x | st3] @ U_all_w, K=2048
    tc_gemm_kernel<<<dim3(8, 256), 256, MMA_SMEM>>>(
        x, 1024, st3, 1024, uT, U_all_b, u, MROWS, 1024, 2048, 0);
    // 7. transpose u to [t][col][b]
    transpose_u_kernel<<<dim3(32, 256, 4), dim3(32, 8)>>>(u);
    // 8. persistent scan
    scan_kernel<<<NBLK_SCAN, 512, scan_smem>>>(tsmp, W_all_w, W_all_b,
                                               W_d_w, W_d_b, feat);
    // 9. classifier
    cls_kernel<<<4096, 256>>>(feat, cls_w, cls_b, out);
}